// round 15
// baseline (speedup 1.0000x reference)
#include <cuda_runtime.h>
#include <cuda_fp16.h>
#include <math.h>
#include <stdint.h>

// Problem constants
#define B_   2
#define L_   2048
#define C_   1024
#define NH_  16
#define HD_  64
#define M_ROWS (B_*L_)          // 4096
#define QKV_N  (3*C_)           // 3072
#define QSC  0.1803368801111204f   // 0.125 * log2(e)

// -------------------- scratch (static device globals) -----------------------
__device__ __half g_q16 [B_*NH_*L_*HD_];      // [b,h,l,d] fp16 (rope'd, pre-scaled Q)
__device__ __half g_kh  [B_*NH_*L_*HD_];      // [b,h,l,d] fp16 (rope'd K)
__device__ __half g_vt  [B_*NH_*HD_*L_];      // [b,h,d,l] fp16 (V transposed)
__device__ __half g_xh  [M_ROWS * C_];        // x fp16 [M,K]
__device__ __half g_wq  [QKV_N * C_];         // Wqkv^T fp16 [N,K]
__device__ __half g_wp  [C_ * C_];            // Wproj^T fp16 [N,K]
__device__ __half g_ah  [M_ROWS * C_];        // attn fp16 [b,l,h,d]
__device__ float2 g_rope[L_ * (HD_/2)];       // (sin, cos) per (l, pair)

// ======================= small helpers =====================================
__device__ __forceinline__ float ex2(float x) {
    float y; asm("ex2.approx.f32 %0, %1;" : "=f"(y) : "f"(x)); return y;
}
__device__ __forceinline__ uint32_t pack2(float a, float b) {
    __half2 h = __floats2half2_rn(a, b);
    return *(uint32_t*)&h;
}
__device__ __forceinline__ void mma16(float* c,
                                      uint32_t a0, uint32_t a1, uint32_t a2, uint32_t a3,
                                      uint32_t b0, uint32_t b1) {
    asm volatile(
        "mma.sync.aligned.m16n8k16.row.col.f32.f16.f16.f32 "
        "{%0,%1,%2,%3}, {%4,%5,%6,%7}, {%8,%9}, {%0,%1,%2,%3};"
        : "+f"(c[0]), "+f"(c[1]), "+f"(c[2]), "+f"(c[3])
        : "r"(a0), "r"(a1), "r"(a2), "r"(a3), "r"(b0), "r"(b1));
}
__device__ __forceinline__ void ldsm4(uint32_t& r0, uint32_t& r1,
                                      uint32_t& r2, uint32_t& r3, uint32_t addr) {
    asm volatile("ldmatrix.sync.aligned.m8n8.x4.shared.b16 {%0,%1,%2,%3}, [%4];"
        : "=r"(r0), "=r"(r1), "=r"(r2), "=r"(r3) : "r"(addr));
}
__device__ __forceinline__ void cpa16(void* smem, const void* gmem) {
    uint32_t s = (uint32_t)__cvta_generic_to_shared(smem);
    asm volatile("cp.async.cg.shared.global [%0], [%1], 16;" :: "r"(s), "l"(gmem));
}
#define CP_COMMIT() asm volatile("cp.async.commit_group;")
#define CP_WAIT0()  asm volatile("cp.async.wait_group 0;")
#define CP_WAIT1()  asm volatile("cp.async.wait_group 1;")

// ======================= merged prepass kernel =============================
__global__ __launch_bounds__(256)
void prep_kernel(const float* __restrict__ Wqkv, const float* __restrict__ Wproj,
                 const float4* __restrict__ x,
                 __half* __restrict__ wq, __half* __restrict__ wp,
                 uint2* __restrict__ xh, float2* __restrict__ rt)
{
    __shared__ float tile[32][33];
    const int bid = blockIdx.x;
    const int t = threadIdx.x;

    if (bid < 4096) {
        const float* in; __half* out; int R, Ccols, bx, by;
        if (bid < 3072) { in = Wqkv; out = wq; R = C_; Ccols = QKV_N; bx = bid % 96; by = bid / 96; }
        else            { in = Wproj; out = wp; R = C_; Ccols = C_;  int bb = bid - 3072; bx = bb % 32; by = bb / 32; }
        int tx = t & 31, ty = t >> 5;
        int c0 = bx * 32, r0 = by * 32;
        #pragma unroll
        for (int j = ty; j < 32; j += 8)
            tile[j][tx] = in[(size_t)(r0 + j) * Ccols + c0 + tx];
        __syncthreads();
        #pragma unroll
        for (int j = ty; j < 32; j += 8)
            out[(size_t)(c0 + j) * R + r0 + tx] = __float2half(tile[tx][j]);
    } else if (bid < 5120) {
        int base = (bid - 4096) * 1024;
        #pragma unroll
        for (int k = 0; k < 4; k++) {
            int i = base + k * 256 + t;
            float4 v = x[i];
            xh[i] = make_uint2(pack2(v.x, v.y), pack2(v.z, v.w));
        }
    } else {
        int idx = (bid - 5120) * 256 + t;    // < 65536
        int l = idx >> 5, i = idx & 31;
        int d0 = 2 * i;
        double inv_freq = exp(-((double)d0 / 64.0) * log(10000.0));
        float theta = (float)((double)l * inv_freq);
        float s, c;
        sincosf(theta, &s, &c);
        rt[idx] = make_float2(s, c);
    }
}

// ======================= FP16 GEMM 128x128x64, 4 warps (64x64) =============
// GBK=64, manual fragment double-buffering: LDSM(ks+1) issued before MMA(ks).
#define GBK 64
#define RSTR 36                         // words per smem row (72 halves, 144 B)
#define TSTW (128 * RSTR)               // 4608 words per operand tile
#define STW  (2 * TSTW)                 // 36,864 B per stage
#define GEMM_SMEM (3 * STW * 4)         // 110,592 B -> 2 CTAs/SM
#define SSTR 136                        // mode-1 staging row stride (halves)
#define FSTR32 132                      // mode-0 staging row stride (floats)

template<int MODE>
__global__ __launch_bounds__(128)
void gemm_fp16(const __half* __restrict__ A, const __half* __restrict__ B,
               float* __restrict__ C,
               __half* __restrict__ Qo, __half* __restrict__ Ko,
               __half* __restrict__ VT,
               const float2* __restrict__ rt,
               int M, int N, int K)
{
    extern __shared__ uint32_t smw[];

    const int t    = threadIdx.x;
    const int lane = t & 31;
    const int warp = t >> 5;
    const int grp  = lane >> 2;
    const int tig  = lane & 3;
    const int wm   = warp >> 1;
    const int wn   = warp & 1;
    const int rowBase = blockIdx.y * 128;
    const int colBase = blockIdx.x * 128;

    const int rowA = (lane & 7) + ((lane >> 3) & 1) * 8;
    const int kA   = ((lane >> 4) & 1) * 8;
    const int rowB = (lane & 7) + ((lane >> 4) & 1) * 8;
    const int kB   = ((lane >> 3) & 1) * 8;

    const uint32_t sbase = (uint32_t)__cvta_generic_to_shared(smw);
    const uint32_t aoff = (uint32_t)((wm * 64 + rowA) * 144 + kA * 2);
    const uint32_t boff = (uint32_t)(TSTW * 4 + (wn * 64 + rowB) * 144 + kB * 2);

    float acc[4][8][4];
    #pragma unroll
    for (int mi = 0; mi < 4; mi++)
        #pragma unroll
        for (int ni = 0; ni < 8; ni++)
            #pragma unroll
            for (int e = 0; e < 4; e++) acc[mi][ni][e] = 0.f;

    const int NIT = K / GBK;            // 16
    #pragma unroll
    for (int s = 0; s < 2; s++) {
        uint32_t* stg = smw + s * STW;
        #pragma unroll
        for (int i = 0; i < 8; i++) {
            int idx = t + i * 128;
            int r = idx >> 3, c = idx & 7;
            cpa16(stg + r * RSTR + c * 4, A + (size_t)(rowBase + r) * K + s * GBK + c * 8);
            cpa16(stg + TSTW + r * RSTR + c * 4,
                  B + (size_t)(colBase + r) * K + s * GBK + c * 8);
        }
        CP_COMMIT();
    }

    uint32_t af[2][4][4], bf[2][8][2];
    int scur = 0;
    for (int it = 0; it < NIT; ++it) {
        if (it < NIT - 1) { CP_WAIT1(); } else { CP_WAIT0(); }
        __syncthreads();

        if (it + 2 < NIT) {
            int snext = scur + 2; if (snext >= 3) snext -= 3;
            uint32_t* stg = smw + snext * STW;
            int k0 = (it + 2) * GBK;
            #pragma unroll
            for (int i = 0; i < 8; i++) {
                int idx = t + i * 128;
                int r = idx >> 3, c = idx & 7;
                cpa16(stg + r * RSTR + c * 4, A + (size_t)(rowBase + r) * K + k0 + c * 8);
                cpa16(stg + TSTW + r * RSTR + c * 4,
                      B + (size_t)(colBase + r) * K + k0 + c * 8);
            }
            CP_COMMIT();
        }

        const uint32_t Abase = sbase + scur * (STW * 4) + aoff;
        const uint32_t Bbase = sbase + scur * (STW * 4) + boff;

        // preload k-step 0 fragments
        #pragma unroll
        for (int mi = 0; mi < 4; mi++)
            ldsm4(af[0][mi][0], af[0][mi][1], af[0][mi][2], af[0][mi][3],
                  Abase + mi * (16 * 144));
        #pragma unroll
        for (int nip = 0; nip < 4; nip++)
            ldsm4(bf[0][2*nip][0], bf[0][2*nip][1], bf[0][2*nip+1][0], bf[0][2*nip+1][1],
                  Bbase + nip * (16 * 144));

        #pragma unroll
        for (int ks = 0; ks < 4; ks++) {
            const int cur = ks & 1, nxt = cur ^ 1;
            if (ks < 3) {               // issue next k-step's LDSMs first
                #pragma unroll
                for (int mi = 0; mi < 4; mi++)
                    ldsm4(af[nxt][mi][0], af[nxt][mi][1], af[nxt][mi][2], af[nxt][mi][3],
                          Abase + mi * (16 * 144) + (ks + 1) * 32);
                #pragma unroll
                for (int nip = 0; nip < 4; nip++)
                    ldsm4(bf[nxt][2*nip][0], bf[nxt][2*nip][1],
                          bf[nxt][2*nip+1][0], bf[nxt][2*nip+1][1],
                          Bbase + nip * (16 * 144) + (ks + 1) * 32);
            }
            #pragma unroll
            for (int mi = 0; mi < 4; mi++)
                #pragma unroll
                for (int ni = 0; ni < 8; ni++)
                    mma16(acc[mi][ni], af[cur][mi][0], af[cur][mi][1],
                          af[cur][mi][2], af[cur][mi][3],
                          bf[cur][ni][0], bf[cur][ni][1]);
        }
        scur++; if (scur >= 3) scur -= 3;
    }

    if (MODE == 0) {
        // staged coalesced fp32 epilogue: two passes of 64 rows
        float* st2 = (float*)smw;
        #pragma unroll
        for (int p = 0; p < 2; p++) {
            __syncthreads();
            if (wm == p) {
                #pragma unroll
                for (int mi = 0; mi < 4; mi++) {
                    #pragma unroll
                    for (int ni = 0; ni < 8; ni++) {
                        int row = mi * 16 + grp;
                        int col = wn * 64 + ni * 8 + 2 * tig;
                        *(float2*)&st2[ row      * FSTR32 + col] = make_float2(acc[mi][ni][0], acc[mi][ni][1]);
                        *(float2*)&st2[(row + 8) * FSTR32 + col] = make_float2(acc[mi][ni][2], acc[mi][ni][3]);
                    }
                }
            }
            __syncthreads();
            #pragma unroll
            for (int i = 0; i < 16; i++) {
                int idx = t + i * 128;         // 2048 float4s
                int r = idx >> 5, c4 = idx & 31;
                float4 v = *(float4*)&st2[r * FSTR32 + c4 * 4];
                *(float4*)&C[(size_t)(rowBase + p * 64 + r) * N + colBase + c4 * 4] = v;
            }
        }
    } else {
        // ---- phase A: stage acc (fp16) into smem [128][SSTR] ----
        __syncthreads();
        __half* st = (__half*)smw;
        #pragma unroll
        for (int mi = 0; mi < 4; mi++) {
            #pragma unroll
            for (int ni = 0; ni < 8; ni++) {
                int row = wm * 64 + mi * 16 + grp;
                int col = wn * 64 + ni * 8 + 2 * tig;
                *(uint32_t*)&st[ row      * SSTR + col] = pack2(acc[mi][ni][0], acc[mi][ni][1]);
                *(uint32_t*)&st[(row + 8) * SSTR + col] = pack2(acc[mi][ni][2], acc[mi][ni][3]);
            }
        }
        __syncthreads();

        // ---- phase B: coalesced output ----
        const int sec = colBase >> 10;          // 0=q 1=k 2=v
        const int h0  = (colBase & 1023) >> 6;
        const int b   = rowBase >> 11;
        const int l0  = rowBase & 2047;

        if (sec < 2) {
            __half* dst = (sec == 0) ? Qo : Ko;
            const float qs = (sec == 0) ? QSC : 1.0f;
            #pragma unroll
            for (int hh = 0; hh < 2; hh++) {
                const int h = h0 + hh;
                for (int idx = t; idx < 1024; idx += 128) {
                    int lrow = idx >> 3;
                    int part = idx & 7;
                    int l = l0 + lrow;
                    uint4 u = *(uint4*)&st[lrow * SSTR + hh * 64 + part * 8];
                    const float2* rp = rt + l * 32 + part * 4;
                    float2 p0 = __half22float2(*(__half2*)&u.x);
                    float2 p1 = __half22float2(*(__half2*)&u.y);
                    float2 p2 = __half22float2(*(__half2*)&u.z);
                    float2 p3 = __half22float2(*(__half2*)&u.w);
                    float2 t0 = rp[0], t1 = rp[1], t2 = rp[2], t3 = rp[3];
                    uint4 o;
                    o.x = pack2((p0.x*t0.x - p0.y*t0.y)*qs, (p0.x*t0.y + p0.y*t0.x)*qs);
                    o.y = pack2((p1.x*t1.x - p1.y*t1.y)*qs, (p1.x*t1.y + p1.y*t1.x)*qs);
                    o.z = pack2((p2.x*t2.x - p2.y*t2.y)*qs, (p2.x*t2.y + p2.y*t2.x)*qs);
                    o.w = pack2((p3.x*t3.x - p3.y*t3.y)*qs, (p3.x*t3.y + p3.y*t3.x)*qs);
                    *(uint4*)&dst[(((size_t)(b*NH_ + h) * L_) + l) * HD_ + part * 8] = o;
                }
            }
        } else {
            for (int idx = t; idx < 2048; idx += 128) {
                int hd   = idx >> 4;
                int part = idx & 15;
                int hh = hd >> 6, d = hd & 63;
                int h = h0 + hh;
                __half vals[8];
                #pragma unroll
                for (int j = 0; j < 8; j++)
                    vals[j] = st[(part * 8 + j) * SSTR + hh * 64 + d];
                *(uint4*)&VT[(((size_t)(b*NH_ + h) * HD_) + d) * L_ + l0 + part * 8] =
                    *(uint4*)vals;
            }
        }
    }
}

// ======================= Flash attention (fp16 mma, causal) ================
// K/V fragments double-buffered: LDSM(ks+1) issued before MMA(ks).
#define FSTR 36                         // words per smem row (72 halves, 144 B)
#define KT_W (64 * FSTR)
#define OFF_VT (2 * KT_W)
#define FA_SMEM (4 * KT_W * 4)          // 36,864 B

__global__ __launch_bounds__(256)
void flash_fp16(const __half* __restrict__ Q, const __half* __restrict__ K,
                const __half* __restrict__ VT, __half* __restrict__ O)
{
    extern __shared__ uint32_t smw[];
    uint32_t* Ksm = smw;
    uint32_t* Vsm = smw + OFF_VT;

    const int t    = threadIdx.x;
    const int lane = t & 31;
    const int warp = t >> 5;
    const int grp  = lane >> 2;
    const int tig  = lane & 3;
    const int qt   = (gridDim.x - 1) - blockIdx.x;
    const int bh   = blockIdx.y;
    const size_t base = (size_t)bh * L_ * HD_;
    const int R0 = qt * 128 + warp * 16;

    const int rowB = (lane & 7) + ((lane >> 4) & 1) * 8;
    const int kB   = ((lane >> 3) & 1) * 8;
    const uint32_t sbase = (uint32_t)__cvta_generic_to_shared(smw);
    const uint32_t lboff = (uint32_t)(rowB * 144 + kB * 2);

    uint32_t aq[4][4];
    {
        const __half* Qp = Q + base + (size_t)R0 * HD_;
        #pragma unroll
        for (int ks = 0; ks < 4; ks++) {
            int c = 16 * ks + 2 * tig;
            aq[ks][0] = *(const uint32_t*)&Qp[(grp    ) * HD_ + c    ];
            aq[ks][1] = *(const uint32_t*)&Qp[(grp + 8) * HD_ + c    ];
            aq[ks][2] = *(const uint32_t*)&Qp[(grp    ) * HD_ + c + 8];
            aq[ks][3] = *(const uint32_t*)&Qp[(grp + 8) * HD_ + c + 8];
        }
    }

    float o[8][4];
    #pragma unroll
    for (int ni = 0; ni < 8; ni++)
        #pragma unroll
        for (int e = 0; e < 4; e++) o[ni][e] = 0.f;
    float mA = -1e30f, mB = -1e30f, lA = 0.f, lB = 0.f;

    const int nkt = 2 * qt + 2;

    {
        const __half* Kg = K + base;
        const __half* Vg = VT + (size_t)bh * HD_ * L_;
        #pragma unroll
        for (int i = 0; i < 2; i++) {
            int idx = t + i * 256;
            int r = idx >> 3, c = idx & 7;
            cpa16(Ksm + r * FSTR + c * 4, Kg + (size_t)r * HD_ + c * 8);
            cpa16(Vsm + r * FSTR + c * 4, Vg + (size_t)r * L_ + c * 8);
        }
        CP_COMMIT();
    }

    uint32_t bf[2][8][2];
    for (int kt = 0; kt < nkt; kt++) {
        const int p = kt & 1;
        CP_WAIT0();
        __syncthreads();

        if (kt + 1 < nkt) {
            const __half* Kg = K + base + (size_t)(kt + 1) * 64 * HD_;
            const __half* Vg = VT + (size_t)bh * HD_ * L_ + (size_t)(kt + 1) * 64;
            uint32_t* Kn = Ksm + (p ^ 1) * KT_W;
            uint32_t* Vn = Vsm + (p ^ 1) * KT_W;
            #pragma unroll
            for (int i = 0; i < 2; i++) {
                int idx = t + i * 256;
                int r = idx >> 3, c = idx & 7;
                cpa16(Kn + r * FSTR + c * 4, Kg + (size_t)r * HD_ + c * 8);
                cpa16(Vn + r * FSTR + c * 4, Vg + (size_t)r * L_ + c * 8);
            }
            CP_COMMIT();
        }

        const uint32_t Kbase = sbase + p * (KT_W * 4) + lboff;
        const uint32_t Vbase = sbase + (OFF_VT + p * KT_W) * 4 + lboff;

        const bool active = (kt * 64 <= R0 + 15);
        if (active) {
            // ---- S = Q K^T, double-buffered K fragments ----
            float s[8][4];
            #pragma unroll
            for (int ni = 0; ni < 8; ni++)
                #pragma unroll
                for (int e = 0; e < 4; e++) s[ni][e] = 0.f;

            #pragma unroll
            for (int nip = 0; nip < 4; nip++)
                ldsm4(bf[0][2*nip][0], bf[0][2*nip][1], bf[0][2*nip+1][0], bf[0][2*nip+1][1],
                      Kbase + nip * (16 * 144));
            #pragma unroll
            for (int ks = 0; ks < 4; ks++) {
                const int cur = ks & 1, nxt = cur ^ 1;
                if (ks < 3) {
                    #pragma unroll
                    for (int nip = 0; nip < 4; nip++)
                        ldsm4(bf[nxt][2*nip][0], bf[nxt][2*nip][1],
                              bf[nxt][2*nip+1][0], bf[nxt][2*nip+1][1],
                              Kbase + nip * (16 * 144) + (ks + 1) * 32);
                }
                #pragma unroll
                for (int ni = 0; ni < 8; ni++)
                    mma16(s[ni], aq[ks][0], aq[ks][1], aq[ks][2], aq[ks][3],
                          bf[cur][ni][0], bf[cur][ni][1]);
            }

            if (kt * 64 + 63 > R0) {
                #pragma unroll
                for (int ni = 0; ni < 8; ni++)
                    #pragma unroll
                    for (int e = 0; e < 4; e++) {
                        int col = kt*64 + ni*8 + 2*tig + (e & 1);
                        int row = R0 + grp + ((e & 2) ? 8 : 0);
                        if (col > row) s[ni][e] = -1e30f;
                    }
            }

            float mxA = -1e30f, mxB = -1e30f;
            #pragma unroll
            for (int ni = 0; ni < 8; ni++) {
                mxA = fmaxf(mxA, fmaxf(s[ni][0], s[ni][1]));
                mxB = fmaxf(mxB, fmaxf(s[ni][2], s[ni][3]));
            }
            mxA = fmaxf(mxA, __shfl_xor_sync(0xffffffffu, mxA, 1));
            mxA = fmaxf(mxA, __shfl_xor_sync(0xffffffffu, mxA, 2));
            mxB = fmaxf(mxB, __shfl_xor_sync(0xffffffffu, mxB, 1));
            mxB = fmaxf(mxB, __shfl_xor_sync(0xffffffffu, mxB, 2));

            float mnA = fmaxf(mA, mxA), mnB = fmaxf(mB, mxB);
            float aA = ex2(mA - mnA), aB = ex2(mB - mnB);
            float sA = 0.f, sB = 0.f;
            #pragma unroll
            for (int ni = 0; ni < 8; ni++) {
                s[ni][0] = ex2(s[ni][0] - mnA);
                s[ni][1] = ex2(s[ni][1] - mnA);
                s[ni][2] = ex2(s[ni][2] - mnB);
                s[ni][3] = ex2(s[ni][3] - mnB);
                sA += s[ni][0] + s[ni][1];
                sB += s[ni][2] + s[ni][3];
            }
            sA += __shfl_xor_sync(0xffffffffu, sA, 1);
            sA += __shfl_xor_sync(0xffffffffu, sA, 2);
            sB += __shfl_xor_sync(0xffffffffu, sB, 1);
            sB += __shfl_xor_sync(0xffffffffu, sB, 2);
            lA = lA * aA + sA;  lB = lB * aB + sB;
            mA = mnA;           mB = mnB;
            #pragma unroll
            for (int ni = 0; ni < 8; ni++) {
                o[ni][0] *= aA; o[ni][1] *= aA;
                o[ni][2] *= aB; o[ni][3] *= aB;
            }

            // ---- O += P V, double-buffered V fragments ----
            #pragma unroll
            for (int nip = 0; nip < 4; nip++)
                ldsm4(bf[0][2*nip][0], bf[0][2*nip][1], bf[0][2*nip+1][0], bf[0][2*nip+1][1],
                      Vbase + nip * (16 * 144));
            #pragma unroll
            for (int ks = 0; ks < 4; ks++) {
                const int cur = ks & 1, nxt = cur ^ 1;
                if (ks < 3) {
                    #pragma unroll
                    for (int nip = 0; nip < 4; nip++)
                        ldsm4(bf[nxt][2*nip][0], bf[nxt][2*nip][1],
                              bf[nxt][2*nip+1][0], bf[nxt][2*nip+1][1],
                              Vbase + nip * (16 * 144) + (ks + 1) * 32);
                }
                uint32_t a0 = pack2(s[2*ks  ][0], s[2*ks  ][1]);
                uint32_t a1 = pack2(s[2*ks  ][2], s[2*ks  ][3]);
                uint32_t a2 = pack2(s[2*ks+1][0], s[2*ks+1][1]);
                uint32_t a3 = pack2(s[2*ks+1][2], s[2*ks+1][3]);
                #pragma unroll
                for (int ni = 0; ni < 8; ni++)
                    mma16(o[ni], a0, a1, a2, a3, bf[cur][ni][0], bf[cur][ni][1]);
            }
        }
    }

    int b = bh >> 4, h = bh & 15;
    float iA = 1.f / lA, iB = 1.f / lB;
    #pragma unroll
    for (int ni = 0; ni < 8; ni++) {
        int c = ni*8 + 2*tig;
        size_t offA = ((size_t)(b*L_ + R0 + grp    )) * C_ + h*HD_ + c;
        size_t offB = ((size_t)(b*L_ + R0 + grp + 8)) * C_ + h*HD_ + c;
        *(uint32_t*)&O[offA] = pack2(o[ni][0]*iA, o[ni][1]*iA);
        *(uint32_t*)&O[offB] = pack2(o[ni][2]*iB, o[ni][3]*iB);
    }
}

// ======================= launcher ==========================================
extern "C" void kernel_launch(void* const* d_in, const int* in_sizes, int n_in,
                              void* d_out, int out_size)
{
    const float* x     = (const float*)d_in[0];
    const float* Wqkv  = (const float*)d_in[1];
    const float* Wproj = (const float*)d_in[2];
    float* out = (float*)d_out;

    __half *q16, *kh, *vt, *xh, *wq, *wp, *ah;
    float2* rt;
    cudaGetSymbolAddress((void**)&q16, g_q16);
    cudaGetSymbolAddress((void**)&kh,  g_kh);
    cudaGetSymbolAddress((void**)&vt,  g_vt);
    cudaGetSymbolAddress((void**)&xh,  g_xh);
    cudaGetSymbolAddress((void**)&wq,  g_wq);
    cudaGetSymbolAddress((void**)&wp,  g_wp);
    cudaGetSymbolAddress((void**)&ah,  g_ah);
    cudaGetSymbolAddress((void**)&rt,  g_rope);

    cudaFuncSetAttribute(gemm_fp16<0>,
                         cudaFuncAttributeMaxDynamicSharedMemorySize, GEMM_SMEM);
    cudaFuncSetAttribute(gemm_fp16<1>,
                         cudaFuncAttributeMaxDynamicSharedMemorySize, GEMM_SMEM);
    cudaFuncSetAttribute(flash_fp16,
                         cudaFuncAttributeMaxDynamicSharedMemorySize, FA_SMEM);

    // 0) merged prepass: weight transposes + x cvt + rope table
    prep_kernel<<<5376, 256>>>(Wqkv, Wproj, (const float4*)x, wq, wp, (uint2*)xh, rt);
    // 1) qkv GEMM, fused rope/split epilogue -> Q(pre-scaled),K [b,h,l,d], VT [b,h,d,l]
    gemm_fp16<1><<<dim3(QKV_N/128, M_ROWS/128), 128, GEMM_SMEM>>>(
        xh, wq, nullptr, q16, kh, vt, rt, M_ROWS, QKV_N, C_);
    // 2) causal flash attention -> attn fp16
    {
        dim3 grid(L_ / 128, B_ * NH_);
        flash_fp16<<<grid, 256, FA_SMEM>>>(q16, kh, vt, ah);
    }
    // 3) out = attn @ Wproj (staged coalesced fp32 epilogue)
    gemm_fp16<0><<<dim3(C_/128, M_ROWS/128), 128, GEMM_SMEM>>>(
        ah, wp, out, nullptr, nullptr, nullptr, nullptr, M_ROWS, C_, C_);
}

// round 16
// speedup vs baseline: 1.0404x; 1.0404x over previous
#include <cuda_runtime.h>
#include <cuda_fp16.h>
#include <math.h>
#include <stdint.h>

// Problem constants
#define B_   2
#define L_   2048
#define C_   1024
#define NH_  16
#define HD_  64
#define M_ROWS (B_*L_)          // 4096
#define QKV_N  (3*C_)           // 3072
#define QSC  0.1803368801111204f   // 0.125 * log2(e)

// -------------------- scratch (static device globals) -----------------------
__device__ __half g_q16 [B_*NH_*L_*HD_];      // [b,h,l,d] fp16 (rope'd, pre-scaled Q)
__device__ __half g_kh  [B_*NH_*L_*HD_];      // [b,h,l,d] fp16 (rope'd K)
__device__ __half g_vt  [B_*NH_*HD_*L_];      // [b,h,d,l] fp16 (V transposed)
__device__ __half g_xh  [M_ROWS * C_];        // x fp16 [M,K]
__device__ __half g_wq  [QKV_N * C_];         // Wqkv^T fp16 [N,K]
__device__ __half g_wp  [C_ * C_];            // Wproj^T fp16 [N,K]
__device__ __half g_ah  [M_ROWS * C_];        // attn fp16 [b,l,h,d]
__device__ float2 g_rope[L_ * (HD_/2)];       // (sin, cos) per (l, pair)

// ======================= small helpers =====================================
__device__ __forceinline__ float ex2(float x) {
    float y; asm("ex2.approx.f32 %0, %1;" : "=f"(y) : "f"(x)); return y;
}
__device__ __forceinline__ uint32_t pack2(float a, float b) {
    __half2 h = __floats2half2_rn(a, b);
    return *(uint32_t*)&h;
}
__device__ __forceinline__ void mma16(float* c,
                                      uint32_t a0, uint32_t a1, uint32_t a2, uint32_t a3,
                                      uint32_t b0, uint32_t b1) {
    asm volatile(
        "mma.sync.aligned.m16n8k16.row.col.f32.f16.f16.f32 "
        "{%0,%1,%2,%3}, {%4,%5,%6,%7}, {%8,%9}, {%0,%1,%2,%3};"
        : "+f"(c[0]), "+f"(c[1]), "+f"(c[2]), "+f"(c[3])
        : "r"(a0), "r"(a1), "r"(a2), "r"(a3), "r"(b0), "r"(b1));
}
__device__ __forceinline__ void ldsm4(uint32_t& r0, uint32_t& r1,
                                      uint32_t& r2, uint32_t& r3, uint32_t addr) {
    asm volatile("ldmatrix.sync.aligned.m8n8.x4.shared.b16 {%0,%1,%2,%3}, [%4];"
        : "=r"(r0), "=r"(r1), "=r"(r2), "=r"(r3) : "r"(addr));
}
__device__ __forceinline__ void cpa16(void* smem, const void* gmem) {
    uint32_t s = (uint32_t)__cvta_generic_to_shared(smem);
    asm volatile("cp.async.cg.shared.global [%0], [%1], 16;" :: "r"(s), "l"(gmem));
}
#define CP_COMMIT() asm volatile("cp.async.commit_group;")
#define CP_WAIT0()  asm volatile("cp.async.wait_group 0;")
#define CP_WAIT1()  asm volatile("cp.async.wait_group 1;")

// ======================= merged prepass kernel =============================
__global__ __launch_bounds__(256)
void prep_kernel(const float* __restrict__ Wqkv, const float* __restrict__ Wproj,
                 const float4* __restrict__ x,
                 __half* __restrict__ wq, __half* __restrict__ wp,
                 uint2* __restrict__ xh, float2* __restrict__ rt)
{
    __shared__ float tile[32][33];
    const int bid = blockIdx.x;
    const int t = threadIdx.x;

    if (bid < 4096) {
        const float* in; __half* out; int R, Ccols, bx, by;
        if (bid < 3072) { in = Wqkv; out = wq; R = C_; Ccols = QKV_N; bx = bid % 96; by = bid / 96; }
        else            { in = Wproj; out = wp; R = C_; Ccols = C_;  int bb = bid - 3072; bx = bb % 32; by = bb / 32; }
        int tx = t & 31, ty = t >> 5;
        int c0 = bx * 32, r0 = by * 32;
        #pragma unroll
        for (int j = ty; j < 32; j += 8)
            tile[j][tx] = in[(size_t)(r0 + j) * Ccols + c0 + tx];
        __syncthreads();
        #pragma unroll
        for (int j = ty; j < 32; j += 8)
            out[(size_t)(c0 + j) * R + r0 + tx] = __float2half(tile[tx][j]);
    } else if (bid < 5120) {
        int base = (bid - 4096) * 1024;
        #pragma unroll
        for (int k = 0; k < 4; k++) {
            int i = base + k * 256 + t;
            float4 v = x[i];
            xh[i] = make_uint2(pack2(v.x, v.y), pack2(v.z, v.w));
        }
    } else {
        int idx = (bid - 5120) * 256 + t;    // < 65536
        int l = idx >> 5, i = idx & 31;
        int d0 = 2 * i;
        double inv_freq = exp(-((double)d0 / 64.0) * log(10000.0));
        float theta = (float)((double)l * inv_freq);
        float s, c;
        sincosf(theta, &s, &c);
        rt[idx] = make_float2(s, c);
    }
}

// ======================= FP16 GEMM 128x128x64, 4 warps (64x64) =============
// GBK=64, fragment double-buffering; frag preload hoisted above prefetch.
#define GBK 64
#define RSTR 36                         // words per smem row (72 halves, 144 B)
#define TSTW (128 * RSTR)               // 4608 words per operand tile
#define STW  (2 * TSTW)                 // 36,864 B per stage
#define GEMM_SMEM (3 * STW * 4)         // 110,592 B -> 2 CTAs/SM
#define SSTR 136                        // mode-1 staging row stride (halves)
#define FSTR32 132                      // mode-0 staging row stride (floats)

template<int MODE>
__global__ __launch_bounds__(128)
void gemm_fp16(const __half* __restrict__ A, const __half* __restrict__ B,
               float* __restrict__ C,
               __half* __restrict__ Qo, __half* __restrict__ Ko,
               __half* __restrict__ VT,
               const float2* __restrict__ rt,
               int M, int N, int K)
{
    extern __shared__ uint32_t smw[];

    const int t    = threadIdx.x;
    const int lane = t & 31;
    const int warp = t >> 5;
    const int grp  = lane >> 2;
    const int tig  = lane & 3;
    const int wm   = warp >> 1;
    const int wn   = warp & 1;
    const int rowBase = blockIdx.y * 128;
    const int colBase = blockIdx.x * 128;

    const int rowA = (lane & 7) + ((lane >> 3) & 1) * 8;
    const int kA   = ((lane >> 4) & 1) * 8;
    const int rowB = (lane & 7) + ((lane >> 4) & 1) * 8;
    const int kB   = ((lane >> 3) & 1) * 8;

    const uint32_t sbase = (uint32_t)__cvta_generic_to_shared(smw);
    const uint32_t aoff = (uint32_t)((wm * 64 + rowA) * 144 + kA * 2);
    const uint32_t boff = (uint32_t)(TSTW * 4 + (wn * 64 + rowB) * 144 + kB * 2);

    float acc[4][8][4];
    #pragma unroll
    for (int mi = 0; mi < 4; mi++)
        #pragma unroll
        for (int ni = 0; ni < 8; ni++)
            #pragma unroll
            for (int e = 0; e < 4; e++) acc[mi][ni][e] = 0.f;

    const int NIT = K / GBK;            // 16
    #pragma unroll
    for (int s = 0; s < 2; s++) {
        uint32_t* stg = smw + s * STW;
        #pragma unroll
        for (int i = 0; i < 8; i++) {
            int idx = t + i * 128;
            int r = idx >> 3, c = idx & 7;
            cpa16(stg + r * RSTR + c * 4, A + (size_t)(rowBase + r) * K + s * GBK + c * 8);
            cpa16(stg + TSTW + r * RSTR + c * 4,
                  B + (size_t)(colBase + r) * K + s * GBK + c * 8);
        }
        CP_COMMIT();
    }

    uint32_t af[2][4][4], bf[2][8][2];
    int scur = 0;
    for (int it = 0; it < NIT; ++it) {
        if (it < NIT - 1) { CP_WAIT1(); } else { CP_WAIT0(); }
        __syncthreads();

        const uint32_t Abase = sbase + scur * (STW * 4) + aoff;
        const uint32_t Bbase = sbase + scur * (STW * 4) + boff;

        // preload k-step 0 fragments FIRST (latency hides behind prefetch issue)
        #pragma unroll
        for (int mi = 0; mi < 4; mi++)
            ldsm4(af[0][mi][0], af[0][mi][1], af[0][mi][2], af[0][mi][3],
                  Abase + mi * (16 * 144));
        #pragma unroll
        for (int nip = 0; nip < 4; nip++)
            ldsm4(bf[0][2*nip][0], bf[0][2*nip][1], bf[0][2*nip+1][0], bf[0][2*nip+1][1],
                  Bbase + nip * (16 * 144));

        if (it + 2 < NIT) {
            int snext = scur + 2; if (snext >= 3) snext -= 3;
            uint32_t* stg = smw + snext * STW;
            int k0 = (it + 2) * GBK;
            #pragma unroll
            for (int i = 0; i < 8; i++) {
                int idx = t + i * 128;
                int r = idx >> 3, c = idx & 7;
                cpa16(stg + r * RSTR + c * 4, A + (size_t)(rowBase + r) * K + k0 + c * 8);
                cpa16(stg + TSTW + r * RSTR + c * 4,
                      B + (size_t)(colBase + r) * K + k0 + c * 8);
            }
            CP_COMMIT();
        }

        #pragma unroll
        for (int ks = 0; ks < 4; ks++) {
            const int cur = ks & 1, nxt = cur ^ 1;
            if (ks < 3) {               // issue next k-step's LDSMs first
                #pragma unroll
                for (int mi = 0; mi < 4; mi++)
                    ldsm4(af[nxt][mi][0], af[nxt][mi][1], af[nxt][mi][2], af[nxt][mi][3],
                          Abase + mi * (16 * 144) + (ks + 1) * 32);
                #pragma unroll
                for (int nip = 0; nip < 4; nip++)
                    ldsm4(bf[nxt][2*nip][0], bf[nxt][2*nip][1],
                          bf[nxt][2*nip+1][0], bf[nxt][2*nip+1][1],
                          Bbase + nip * (16 * 144) + (ks + 1) * 32);
            }
            #pragma unroll
            for (int mi = 0; mi < 4; mi++)
                #pragma unroll
                for (int ni = 0; ni < 8; ni++)
                    mma16(acc[mi][ni], af[cur][mi][0], af[cur][mi][1],
                          af[cur][mi][2], af[cur][mi][3],
                          bf[cur][ni][0], bf[cur][ni][1]);
        }
        scur++; if (scur >= 3) scur -= 3;
    }

    if (MODE == 0) {
        // single-pass staged coalesced fp32 epilogue (128x132 = 67.6 KB)
        float* st2 = (float*)smw;
        __syncthreads();
        #pragma unroll
        for (int mi = 0; mi < 4; mi++) {
            #pragma unroll
            for (int ni = 0; ni < 8; ni++) {
                int row = wm * 64 + mi * 16 + grp;
                int col = wn * 64 + ni * 8 + 2 * tig;
                *(float2*)&st2[ row      * FSTR32 + col] = make_float2(acc[mi][ni][0], acc[mi][ni][1]);
                *(float2*)&st2[(row + 8) * FSTR32 + col] = make_float2(acc[mi][ni][2], acc[mi][ni][3]);
            }
        }
        __syncthreads();
        #pragma unroll
        for (int i = 0; i < 32; i++) {
            int idx = t + i * 128;             // 4096 float4s
            int r = idx >> 5, c4 = idx & 31;
            float4 v = *(float4*)&st2[r * FSTR32 + c4 * 4];
            *(float4*)&C[(size_t)(rowBase + r) * N + colBase + c4 * 4] = v;
        }
    } else {
        // ---- phase A: stage acc (fp16) into smem [128][SSTR] ----
        __syncthreads();
        __half* st = (__half*)smw;
        #pragma unroll
        for (int mi = 0; mi < 4; mi++) {
            #pragma unroll
            for (int ni = 0; ni < 8; ni++) {
                int row = wm * 64 + mi * 16 + grp;
                int col = wn * 64 + ni * 8 + 2 * tig;
                *(uint32_t*)&st[ row      * SSTR + col] = pack2(acc[mi][ni][0], acc[mi][ni][1]);
                *(uint32_t*)&st[(row + 8) * SSTR + col] = pack2(acc[mi][ni][2], acc[mi][ni][3]);
            }
        }
        __syncthreads();

        // ---- phase B: coalesced output ----
        const int sec = colBase >> 10;          // 0=q 1=k 2=v
        const int h0  = (colBase & 1023) >> 6;
        const int b   = rowBase >> 11;
        const int l0  = rowBase & 2047;

        if (sec < 2) {
            __half* dst = (sec == 0) ? Qo : Ko;
            const float qs = (sec == 0) ? QSC : 1.0f;
            #pragma unroll
            for (int hh = 0; hh < 2; hh++) {
                const int h = h0 + hh;
                for (int idx = t; idx < 1024; idx += 128) {
                    int lrow = idx >> 3;
                    int part = idx & 7;
                    int l = l0 + lrow;
                    uint4 u = *(uint4*)&st[lrow * SSTR + hh * 64 + part * 8];
                    const float2* rp = rt + l * 32 + part * 4;
                    float2 p0 = __half22float2(*(__half2*)&u.x);
                    float2 p1 = __half22float2(*(__half2*)&u.y);
                    float2 p2 = __half22float2(*(__half2*)&u.z);
                    float2 p3 = __half22float2(*(__half2*)&u.w);
                    float2 t0 = rp[0], t1 = rp[1], t2 = rp[2], t3 = rp[3];
                    uint4 o;
                    o.x = pack2((p0.x*t0.x - p0.y*t0.y)*qs, (p0.x*t0.y + p0.y*t0.x)*qs);
                    o.y = pack2((p1.x*t1.x - p1.y*t1.y)*qs, (p1.x*t1.y + p1.y*t1.x)*qs);
                    o.z = pack2((p2.x*t2.x - p2.y*t2.y)*qs, (p2.x*t2.y + p2.y*t2.x)*qs);
                    o.w = pack2((p3.x*t3.x - p3.y*t3.y)*qs, (p3.x*t3.y + p3.y*t3.x)*qs);
                    *(uint4*)&dst[(((size_t)(b*NH_ + h) * L_) + l) * HD_ + part * 8] = o;
                }
            }
        } else {
            for (int idx = t; idx < 2048; idx += 128) {
                int hd   = idx >> 4;
                int part = idx & 15;
                int hh = hd >> 6, d = hd & 63;
                int h = h0 + hh;
                __half vals[8];
                #pragma unroll
                for (int j = 0; j < 8; j++)
                    vals[j] = st[(part * 8 + j) * SSTR + hh * 64 + d];
                *(uint4*)&VT[(((size_t)(b*NH_ + h) * HD_) + d) * L_ + l0 + part * 8] =
                    *(uint4*)vals;
            }
        }
    }
}

// ======================= Flash attention (fp16 mma, causal) ================
// (R14 version — no fragment double-buffering; it regressed here.)
#define FSTR 36                         // words per smem row (72 halves, 144 B)
#define KT_W (64 * FSTR)
#define OFF_VT (2 * KT_W)
#define FA_SMEM (4 * KT_W * 4)          // 36,864 B

__global__ __launch_bounds__(256)
void flash_fp16(const __half* __restrict__ Q, const __half* __restrict__ K,
                const __half* __restrict__ VT, __half* __restrict__ O)
{
    extern __shared__ uint32_t smw[];
    uint32_t* Ksm = smw;
    uint32_t* Vsm = smw + OFF_VT;

    const int t    = threadIdx.x;
    const int lane = t & 31;
    const int warp = t >> 5;
    const int grp  = lane >> 2;
    const int tig  = lane & 3;
    const int qt   = (gridDim.x - 1) - blockIdx.x;
    const int bh   = blockIdx.y;
    const size_t base = (size_t)bh * L_ * HD_;
    const int R0 = qt * 128 + warp * 16;

    const int rowB = (lane & 7) + ((lane >> 4) & 1) * 8;
    const int kB   = ((lane >> 3) & 1) * 8;
    const uint32_t sbase = (uint32_t)__cvta_generic_to_shared(smw);
    const uint32_t lboff = (uint32_t)(rowB * 144 + kB * 2);

    uint32_t aq[4][4];
    {
        const __half* Qp = Q + base + (size_t)R0 * HD_;
        #pragma unroll
        for (int ks = 0; ks < 4; ks++) {
            int c = 16 * ks + 2 * tig;
            aq[ks][0] = *(const uint32_t*)&Qp[(grp    ) * HD_ + c    ];
            aq[ks][1] = *(const uint32_t*)&Qp[(grp + 8) * HD_ + c    ];
            aq[ks][2] = *(const uint32_t*)&Qp[(grp    ) * HD_ + c + 8];
            aq[ks][3] = *(const uint32_t*)&Qp[(grp + 8) * HD_ + c + 8];
        }
    }

    float o[8][4];
    #pragma unroll
    for (int ni = 0; ni < 8; ni++)
        #pragma unroll
        for (int e = 0; e < 4; e++) o[ni][e] = 0.f;
    float mA = -1e30f, mB = -1e30f, lA = 0.f, lB = 0.f;

    const int nkt = 2 * qt + 2;

    {
        const __half* Kg = K + base;
        const __half* Vg = VT + (size_t)bh * HD_ * L_;
        #pragma unroll
        for (int i = 0; i < 2; i++) {
            int idx = t + i * 256;
            int r = idx >> 3, c = idx & 7;
            cpa16(Ksm + r * FSTR + c * 4, Kg + (size_t)r * HD_ + c * 8);
            cpa16(Vsm + r * FSTR + c * 4, Vg + (size_t)r * L_ + c * 8);
        }
        CP_COMMIT();
    }

    for (int kt = 0; kt < nkt; kt++) {
        const int p = kt & 1;
        CP_WAIT0();
        __syncthreads();

        if (kt + 1 < nkt) {
            const __half* Kg = K + base + (size_t)(kt + 1) * 64 * HD_;
            const __half* Vg = VT + (size_t)bh * HD_ * L_ + (size_t)(kt + 1) * 64;
            uint32_t* Kn = Ksm + (p ^ 1) * KT_W;
            uint32_t* Vn = Vsm + (p ^ 1) * KT_W;
            #pragma unroll
            for (int i = 0; i < 2; i++) {
                int idx = t + i * 256;
                int r = idx >> 3, c = idx & 7;
                cpa16(Kn + r * FSTR + c * 4, Kg + (size_t)r * HD_ + c * 8);
                cpa16(Vn + r * FSTR + c * 4, Vg + (size_t)r * L_ + c * 8);
            }
            CP_COMMIT();
        }

        const uint32_t Kbase = sbase + p * (KT_W * 4) + lboff;
        const uint32_t Vbase = sbase + (OFF_VT + p * KT_W) * 4 + lboff;

        const bool active = (kt * 64 <= R0 + 15);
        if (active) {
            float s[8][4];
            #pragma unroll
            for (int ni = 0; ni < 8; ni++)
                #pragma unroll
                for (int e = 0; e < 4; e++) s[ni][e] = 0.f;

            #pragma unroll
            for (int ks = 0; ks < 4; ks++) {
                uint32_t bf[8][2];
                #pragma unroll
                for (int nip = 0; nip < 4; nip++)
                    ldsm4(bf[2*nip][0], bf[2*nip][1], bf[2*nip+1][0], bf[2*nip+1][1],
                          Kbase + nip * (16 * 144) + ks * 32);
                #pragma unroll
                for (int ni = 0; ni < 8; ni++)
                    mma16(s[ni], aq[ks][0], aq[ks][1], aq[ks][2], aq[ks][3],
                          bf[ni][0], bf[ni][1]);
            }

            if (kt * 64 + 63 > R0) {
                #pragma unroll
                for (int ni = 0; ni < 8; ni++)
                    #pragma unroll
                    for (int e = 0; e < 4; e++) {
                        int col = kt*64 + ni*8 + 2*tig + (e & 1);
                        int row = R0 + grp + ((e & 2) ? 8 : 0);
                        if (col > row) s[ni][e] = -1e30f;
                    }
            }

            float mxA = -1e30f, mxB = -1e30f;
            #pragma unroll
            for (int ni = 0; ni < 8; ni++) {
                mxA = fmaxf(mxA, fmaxf(s[ni][0], s[ni][1]));
                mxB = fmaxf(mxB, fmaxf(s[ni][2], s[ni][3]));
            }
            mxA = fmaxf(mxA, __shfl_xor_sync(0xffffffffu, mxA, 1));
            mxA = fmaxf(mxA, __shfl_xor_sync(0xffffffffu, mxA, 2));
            mxB = fmaxf(mxB, __shfl_xor_sync(0xffffffffu, mxB, 1));
            mxB = fmaxf(mxB, __shfl_xor_sync(0xffffffffu, mxB, 2));

            float mnA = fmaxf(mA, mxA), mnB = fmaxf(mB, mxB);
            float aA = ex2(mA - mnA), aB = ex2(mB - mnB);
            float sA = 0.f, sB = 0.f;
            #pragma unroll
            for (int ni = 0; ni < 8; ni++) {
                s[ni][0] = ex2(s[ni][0] - mnA);
                s[ni][1] = ex2(s[ni][1] - mnA);
                s[ni][2] = ex2(s[ni][2] - mnB);
                s[ni][3] = ex2(s[ni][3] - mnB);
                sA += s[ni][0] + s[ni][1];
                sB += s[ni][2] + s[ni][3];
            }
            sA += __shfl_xor_sync(0xffffffffu, sA, 1);
            sA += __shfl_xor_sync(0xffffffffu, sA, 2);
            sB += __shfl_xor_sync(0xffffffffu, sB, 1);
            sB += __shfl_xor_sync(0xffffffffu, sB, 2);
            lA = lA * aA + sA;  lB = lB * aB + sB;
            mA = mnA;           mB = mnB;
            #pragma unroll
            for (int ni = 0; ni < 8; ni++) {
                o[ni][0] *= aA; o[ni][1] *= aA;
                o[ni][2] *= aB; o[ni][3] *= aB;
            }

            #pragma unroll
            for (int ks = 0; ks < 4; ks++) {
                uint32_t a0 = pack2(s[2*ks  ][0], s[2*ks  ][1]);
                uint32_t a1 = pack2(s[2*ks  ][2], s[2*ks  ][3]);
                uint32_t a2 = pack2(s[2*ks+1][0], s[2*ks+1][1]);
                uint32_t a3 = pack2(s[2*ks+1][2], s[2*ks+1][3]);
                uint32_t bf[8][2];
                #pragma unroll
                for (int nip = 0; nip < 4; nip++)
                    ldsm4(bf[2*nip][0], bf[2*nip][1], bf[2*nip+1][0], bf[2*nip+1][1],
                          Vbase + nip * (16 * 144) + ks * 32);
                #pragma unroll
                for (int ni = 0; ni < 8; ni++)
                    mma16(o[ni], a0, a1, a2, a3, bf[ni][0], bf[ni][1]);
            }
        }
    }

    int b = bh >> 4, h = bh & 15;
    float iA = 1.f / lA, iB = 1.f / lB;
    #pragma unroll
    for (int ni = 0; ni < 8; ni++) {
        int c = ni*8 + 2*tig;
        size_t offA = ((size_t)(b*L_ + R0 + grp    )) * C_ + h*HD_ + c;
        size_t offB = ((size_t)(b*L_ + R0 + grp + 8)) * C_ + h*HD_ + c;
        *(uint32_t*)&O[offA] = pack2(o[ni][0]*iA, o[ni][1]*iA);
        *(uint32_t*)&O[offB] = pack2(o[ni][2]*iB, o[ni][3]*iB);
    }
}

// ======================= launcher ==========================================
extern "C" void kernel_launch(void* const* d_in, const int* in_sizes, int n_in,
                              void* d_out, int out_size)
{
    const float* x     = (const float*)d_in[0];
    const float* Wqkv  = (const float*)d_in[1];
    const float* Wproj = (const float*)d_in[2];
    float* out = (float*)d_out;

    __half *q16, *kh, *vt, *xh, *wq, *wp, *ah;
    float2* rt;
    cudaGetSymbolAddress((void**)&q16, g_q16);
    cudaGetSymbolAddress((void**)&kh,  g_kh);
    cudaGetSymbolAddress((void**)&vt,  g_vt);
    cudaGetSymbolAddress((void**)&xh,  g_xh);
    cudaGetSymbolAddress((void**)&wq,  g_wq);
    cudaGetSymbolAddress((void**)&wp,  g_wp);
    cudaGetSymbolAddress((void**)&ah,  g_ah);
    cudaGetSymbolAddress((void**)&rt,  g_rope);

    cudaFuncSetAttribute(gemm_fp16<0>,
                         cudaFuncAttributeMaxDynamicSharedMemorySize, GEMM_SMEM);
    cudaFuncSetAttribute(gemm_fp16<1>,
                         cudaFuncAttributeMaxDynamicSharedMemorySize, GEMM_SMEM);
    cudaFuncSetAttribute(flash_fp16,
                         cudaFuncAttributeMaxDynamicSharedMemorySize, FA_SMEM);

    // 0) merged prepass: weight transposes + x cvt + rope table
    prep_kernel<<<5376, 256>>>(Wqkv, Wproj, (const float4*)x, wq, wp, (uint2*)xh, rt);
    // 1) qkv GEMM, fused rope/split epilogue -> Q(pre-scaled),K [b,h,l,d], VT [b,h,d,l]
    gemm_fp16<1><<<dim3(QKV_N/128, M_ROWS/128), 128, GEMM_SMEM>>>(
        xh, wq, nullptr, q16, kh, vt, rt, M_ROWS, QKV_N, C_);
    // 2) causal flash attention -> attn fp16
    {
        dim3 grid(L_ / 128, B_ * NH_);
        flash_fp16<<<grid, 256, FA_SMEM>>>(q16, kh, vt, ah);
    }
    // 3) out = attn @ Wproj (single-pass staged fp32 epilogue)
    gemm_fp16<0><<<dim3(C_/128, M_ROWS/128), 128, GEMM_SMEM>>>(
        ah, wp, out, nullptr, nullptr, nullptr, nullptr, M_ROWS, C_, C_);
}